// round 3
// baseline (speedup 1.0000x reference)
#include <cuda_runtime.h>
#include <math.h>

#define T_TOK 4096
#define DIM   512
#define HID   2048
#define NE    16
#define TOPK  2

#define BM 128
#define BN 128
#define BK 32

// ---------------- device scratch (static: no allocation) ----------------
__device__ int   g_count[NE];
__device__ int   g_offset[NE];
__device__ int   g_tok[NE * T_TOK];
__device__ float g_H[(size_t)(2 * T_TOK + BM) * HID];   // compact rows + pad

// ---------------- init: zero out region + counters ----------------
__global__ void init_kernel(float* out) {
    int idx = blockIdx.x * blockDim.x + threadIdx.x;
    int total = T_TOK * DIM;
    if (idx < total) out[idx] = 0.0f;
    if (idx < NE) g_count[idx] = 0;
}

// ---------------- gate: logits, top-2, scores, expert lists ----------------
__global__ void gate_kernel(const float* __restrict__ x,
                            const float* __restrict__ Wg,
                            const float* __restrict__ bg,
                            float* __restrict__ out, int out_size) {
    int t = blockIdx.x;
    int tid = threadIdx.x;          // 128 threads
    int e = tid & 15;
    int g = tid >> 4;               // 0..7
    const float* xr = x + (size_t)t * DIM;

    float s = 0.0f;
    for (int d = g; d < DIM; d += 8)
        s += xr[d] * Wg[d * NE + e];

    __shared__ float buf[128];
    __shared__ float logits[NE];
    buf[tid] = s;
    __syncthreads();
    if (g == 0) {
        float l = bg[e];
        #pragma unroll
        for (int j = 0; j < 8; j++) l += buf[j * 16 + e];
        logits[e] = l;
    }
    __syncthreads();

    if (tid == 0) {
        // top-1
        int i0 = 0; float v0 = logits[0];
        #pragma unroll
        for (int k = 1; k < NE; k++)
            if (logits[k] > v0) { v0 = logits[k]; i0 = k; }
        // top-2 (exclude i0; strict > keeps lowest index on ties)
        int i1 = -1; float v1 = -1e30f;
        #pragma unroll
        for (int k = 0; k < NE; k++)
            if (k != i0 && logits[k] > v1) { v1 = logits[k]; i1 = k; }

        // softmax over the two selected (v0 >= v1)
        float e1 = __expf(v1 - v0);
        float inv = 1.0f / (1.0f + e1);
        float s0 = inv, s1 = e1 * inv;

        const int base_idx = T_TOK * DIM;
        const int base_sc  = T_TOK * DIM + T_TOK * TOPK;
        if (out_size >= base_idx + T_TOK * TOPK) {
            out[base_idx + t * TOPK + 0] = (float)i0;
            out[base_idx + t * TOPK + 1] = (float)i1;
        }
        if (out_size >= base_sc + T_TOK * TOPK) {
            out[base_sc + t * TOPK + 0] = s0;
            out[base_sc + t * TOPK + 1] = s1;
        }

        int slot0 = atomicAdd(&g_count[i0], 1);
        g_tok[i0 * T_TOK + slot0] = t;
        int slot1 = atomicAdd(&g_count[i1], 1);
        g_tok[i1 * T_TOK + slot1] = t;
    }
}

// ---------------- prefix sum over expert counts ----------------
__global__ void prefix_kernel() {
    if (threadIdx.x == 0 && blockIdx.x == 0) {
        int s = 0;
        for (int e = 0; e < NE; e++) { g_offset[e] = s; s += g_count[e]; }
    }
}

// ---------------- GEMM1: H = gelu(x[toks] @ W1[e] + b1[e]) ----------------
__global__ __launch_bounds__(256, 2)
void gemm1_kernel(const float* __restrict__ x,
                  const float* __restrict__ W1,
                  const float* __restrict__ b1) {
    int e   = blockIdx.z;
    int cnt = g_count[e];
    int r0  = blockIdx.y * BM;
    if (r0 >= cnt) return;
    int n0   = blockIdx.x * BN;
    int base = g_offset[e];
    const int* toks = g_tok + e * T_TOK;
    const float* Wb = W1 + (size_t)e * DIM * HID;

    __shared__ float As[BK][BM];
    __shared__ float Bs[BK][BN];

    int tx = threadIdx.x;
    int tr = tx >> 4, tc = tx & 15;

    float acc[8][8];
    #pragma unroll
    for (int i = 0; i < 8; i++)
        #pragma unroll
        for (int j = 0; j < 8; j++) acc[i][j] = 0.0f;

    for (int k0 = 0; k0 < DIM; k0 += BK) {
        #pragma unroll
        for (int i = 0; i < 4; i++) {
            int idx = tx + 256 * i;
            int m = idx >> 3, kq = idx & 7;
            int tg = toks[r0 + m];              // stale slots hold valid token ids
            float4 v = *(const float4*)(x + (size_t)tg * DIM + k0 + kq * 4);
            As[kq * 4 + 0][m] = v.x; As[kq * 4 + 1][m] = v.y;
            As[kq * 4 + 2][m] = v.z; As[kq * 4 + 3][m] = v.w;
        }
        #pragma unroll
        for (int i = 0; i < 4; i++) {
            int idx = tx + 256 * i;
            int kk = idx >> 5, n4 = idx & 31;
            *(float4*)&Bs[kk][n4 * 4] =
                *(const float4*)(Wb + (size_t)(k0 + kk) * HID + n0 + n4 * 4);
        }
        __syncthreads();
        #pragma unroll
        for (int k = 0; k < BK; k++) {
            float a[8], b[8];
            *(float4*)&a[0] = *(const float4*)&As[k][tr * 4];
            *(float4*)&a[4] = *(const float4*)&As[k][64 + tr * 4];
            *(float4*)&b[0] = *(const float4*)&Bs[k][tc * 4];
            *(float4*)&b[4] = *(const float4*)&Bs[k][64 + tc * 4];
            #pragma unroll
            for (int i = 0; i < 8; i++)
                #pragma unroll
                for (int j = 0; j < 8; j++)
                    acc[i][j] += a[i] * b[j];
        }
        __syncthreads();
    }

    const float* b1e = b1 + (size_t)e * HID;
    #pragma unroll
    for (int i = 0; i < 8; i++) {
        int m = (i < 4) ? (tr * 4 + i) : (64 + tr * 4 + (i - 4));
        int slot = r0 + m;
        if (slot >= cnt) continue;
        float* Hp = g_H + (size_t)(base + slot) * HID + n0;
        #pragma unroll
        for (int j = 0; j < 8; j++) {
            int n = (j < 4) ? (tc * 4 + j) : (64 + tc * 4 + (j - 4));
            float v = acc[i][j] + b1e[n0 + n];
            // JAX gelu (approximate=True, tanh form)
            float u = 0.7978845608028654f * (v + 0.044715f * v * v * v);
            Hp[n] = 0.5f * v * (1.0f + tanhf(u));
        }
    }
}

// ---------------- GEMM2: out[tok] += H @ W2[e] + b2[e] ----------------
__global__ __launch_bounds__(256, 2)
void gemm2_kernel(const float* __restrict__ W2,
                  const float* __restrict__ b2,
                  float* __restrict__ out) {
    int e   = blockIdx.z;
    int cnt = g_count[e];
    int r0  = blockIdx.y * BM;
    if (r0 >= cnt) return;
    int n0   = blockIdx.x * BN;
    int base = g_offset[e];
    const int* toks = g_tok + e * T_TOK;
    const float* Wb = W2 + (size_t)e * HID * DIM;

    __shared__ float As[BK][BM];
    __shared__ float Bs[BK][BN];

    int tx = threadIdx.x;
    int tr = tx >> 4, tc = tx & 15;

    float acc[8][8];
    #pragma unroll
    for (int i = 0; i < 8; i++)
        #pragma unroll
        for (int j = 0; j < 8; j++) acc[i][j] = 0.0f;

    for (int k0 = 0; k0 < HID; k0 += BK) {
        #pragma unroll
        for (int i = 0; i < 4; i++) {
            int idx = tx + 256 * i;
            int m = idx >> 3, kq = idx & 7;
            float4 v = *(const float4*)(g_H + (size_t)(base + r0 + m) * HID + k0 + kq * 4);
            As[kq * 4 + 0][m] = v.x; As[kq * 4 + 1][m] = v.y;
            As[kq * 4 + 2][m] = v.z; As[kq * 4 + 3][m] = v.w;
        }
        #pragma unroll
        for (int i = 0; i < 4; i++) {
            int idx = tx + 256 * i;
            int kk = idx >> 5, n4 = idx & 31;
            *(float4*)&Bs[kk][n4 * 4] =
                *(const float4*)(Wb + (size_t)(k0 + kk) * DIM + n0 + n4 * 4);
        }
        __syncthreads();
        #pragma unroll
        for (int k = 0; k < BK; k++) {
            float a[8], b[8];
            *(float4*)&a[0] = *(const float4*)&As[k][tr * 4];
            *(float4*)&a[4] = *(const float4*)&As[k][64 + tr * 4];
            *(float4*)&b[0] = *(const float4*)&Bs[k][tc * 4];
            *(float4*)&b[4] = *(const float4*)&Bs[k][64 + tc * 4];
            #pragma unroll
            for (int i = 0; i < 8; i++)
                #pragma unroll
                for (int j = 0; j < 8; j++)
                    acc[i][j] += a[i] * b[j];
        }
        __syncthreads();
    }

    const float* b2e = b2 + (size_t)e * DIM;
    #pragma unroll
    for (int i = 0; i < 8; i++) {
        int m = (i < 4) ? (tr * 4 + i) : (64 + tr * 4 + (i - 4));
        int slot = r0 + m;
        if (slot >= cnt) continue;
        int tok = toks[slot];
        float* op = out + (size_t)tok * DIM + n0;
        #pragma unroll
        for (int j = 0; j < 8; j++) {
            int n = (j < 4) ? (tc * 4 + j) : (64 + tc * 4 + (j - 4));
            atomicAdd(&op[n], acc[i][j] + b2e[n0 + n]);
        }
    }
}

// ---------------- launch ----------------
extern "C" void kernel_launch(void* const* d_in, const int* in_sizes, int n_in,
                              void* d_out, int out_size) {
    const float* x  = (const float*)d_in[0];
    const float* Wg = (const float*)d_in[1];
    const float* bg = (const float*)d_in[2];
    const float* W1 = (const float*)d_in[3];
    const float* b1 = (const float*)d_in[4];
    const float* W2 = (const float*)d_in[5];
    const float* b2 = (const float*)d_in[6];
    float* out = (float*)d_out;

    int total = T_TOK * DIM;
    init_kernel<<<(total + 255) / 256, 256>>>(out);
    gate_kernel<<<T_TOK, 128>>>(x, Wg, bg, out, out_size);
    prefix_kernel<<<1, 32>>>();
    gemm1_kernel<<<dim3(HID / BN, T_TOK / BM, NE), 256>>>(x, W1, b1);
    gemm2_kernel<<<dim3(DIM / BN, T_TOK / BM, NE), 256>>>(W2, b2, out);
}

// round 10
// speedup vs baseline: 1.3315x; 1.3315x over previous
#include <cuda_runtime.h>
#include <cuda_bf16.h>
#include <stdint.h>
#include <math.h>

#define T_TOK 4096
#define DIM   512
#define HID   2048
#define NE    16

// ======================= device scratch (static, force-aligned) =======================
__device__ __align__(128) int   g_count[NE];
__device__ __align__(128) int   g_offset[NE];
__device__ __align__(128) int   g_ntiles;
__device__ __align__(128) int   g_tiles[128];
__device__ __align__(128) int   g_tok[NE * T_TOK];
__device__ __align__(128) float g_hf[(size_t)(2 * T_TOK + 128) * HID];
__device__ __align__(128) __nv_bfloat16 g_w1_hi[(size_t)NE * HID * DIM];  // [E][n=H][k=D]
__device__ __align__(128) __nv_bfloat16 g_w1_lo[(size_t)NE * HID * DIM];

// ======================= helpers =======================
__device__ __forceinline__ void mma_bf16(float* d, const uint32_t* a, const uint32_t* b) {
    asm volatile(
        "mma.sync.aligned.m16n8k16.row.col.f32.bf16.bf16.f32 "
        "{%0,%1,%2,%3}, {%4,%5,%6,%7}, {%8,%9}, {%0,%1,%2,%3};"
        : "+f"(d[0]), "+f"(d[1]), "+f"(d[2]), "+f"(d[3])
        : "r"(a[0]), "r"(a[1]), "r"(a[2]), "r"(a[3]), "r"(b[0]), "r"(b[1]));
}
__device__ __forceinline__ float gelu_tanh(float v) {
    float u = 0.7978845608028654f * (v + 0.044715f * v * v * v);
    return 0.5f * v * (1.0f + tanhf(u));
}
__device__ __forceinline__ uint32_t packbf2(float a, float b) {
    __nv_bfloat162 t = __floats2bfloat162_rn(a, b);
    return *(uint32_t*)&t;
}

// ======================= init: zero out region + counters =======================
__global__ void init_kernel(float* out) {
    int idx = blockIdx.x * blockDim.x + threadIdx.x;
    if (idx < T_TOK * DIM) out[idx] = 0.0f;
    if (idx < NE) g_count[idx] = 0;
}

// ======================= gate (R3-proven) =======================
__global__ void gate_kernel(const float* __restrict__ x,
                            const float* __restrict__ Wg,
                            const float* __restrict__ bg,
                            float* __restrict__ out, int out_size) {
    int t = blockIdx.x;
    int tid = threadIdx.x;          // 128 threads
    int e = tid & 15;
    int g = tid >> 4;               // 0..7
    const float* xr = x + (size_t)t * DIM;

    float s = 0.0f;
    for (int d = g; d < DIM; d += 8)
        s += xr[d] * Wg[d * NE + e];

    __shared__ float buf[128];
    __shared__ float logits[NE];
    buf[tid] = s;
    __syncthreads();
    if (g == 0) {
        float l = bg[e];
        #pragma unroll
        for (int j = 0; j < 8; j++) l += buf[j * 16 + e];
        logits[e] = l;
    }
    __syncthreads();

    if (tid == 0) {
        int i0 = 0; float v0 = logits[0];
        #pragma unroll
        for (int k = 1; k < NE; k++)
            if (logits[k] > v0) { v0 = logits[k]; i0 = k; }
        int i1 = -1; float v1 = -1e30f;
        #pragma unroll
        for (int k = 0; k < NE; k++)
            if (k != i0 && logits[k] > v1) { v1 = logits[k]; i1 = k; }

        float e1 = __expf(v1 - v0);
        float inv = 1.0f / (1.0f + e1);

        const int base_idx = T_TOK * DIM;
        const int base_sc  = T_TOK * DIM + T_TOK * 2;
        if (out_size >= base_idx + T_TOK * 2) {
            out[base_idx + t * 2 + 0] = (float)i0;
            out[base_idx + t * 2 + 1] = (float)i1;
        }
        if (out_size >= base_sc + T_TOK * 2) {
            out[base_sc + t * 2 + 0] = inv;
            out[base_sc + t * 2 + 1] = e1 * inv;
        }

        int slot0 = atomicAdd(&g_count[i0], 1);
        g_tok[i0 * T_TOK + slot0] = t;
        int slot1 = atomicAdd(&g_count[i1], 1);
        g_tok[i1 * T_TOK + slot1] = t;
    }
}

// ======================= prefix: unpadded offsets + gemm1 tile list =======================
__global__ void prefix_kernel() {
    if (threadIdx.x == 0 && blockIdx.x == 0) {
        int s = 0, nt = 0;
        for (int e = 0; e < NE; e++) {
            g_offset[e] = s;
            int cnt = g_count[e];
            for (int m = 0; m < cnt; m += 128) g_tiles[nt++] = (e << 16) | (m >> 7);
            s += cnt;
        }
        g_ntiles = nt;
    }
}

// ======================= W1 transpose + fp32->bf16 hi/lo split =======================
// src [e][k=DIM][n=HID] row-major -> dst [e][n][k]
__global__ void transpose_split_w1(const float* __restrict__ src) {
    __shared__ float tile[32][33];
    int e = blockIdx.z;
    const float* S = src + (size_t)e * DIM * HID;
    int c0 = blockIdx.x * 32, r0 = blockIdx.y * 32;   // c:n, r:k
    int tx = threadIdx.x, ty = threadIdx.y;
    #pragma unroll
    for (int i = 0; i < 4; i++)
        tile[ty + i * 8][tx] = S[(size_t)(r0 + ty + i * 8) * HID + c0 + tx];
    __syncthreads();
    size_t Dbase = (size_t)e * HID * DIM;
    #pragma unroll
    for (int i = 0; i < 4; i++) {
        int c = c0 + ty + i * 8;                       // n
        float v = tile[tx][ty + i * 8];                // src(r0+tx, c)
        size_t o = Dbase + (size_t)c * DIM + r0 + tx;  // [n][k]
        __nv_bfloat16 h = __float2bfloat16(v);
        g_w1_hi[o] = h;
        g_w1_lo[o] = __float2bfloat16(v - __bfloat162float(h));
    }
}

// ======================= GEMM1: mma.sync bf16 hi/lo, direct-LDS fragments =======================
// 128x128 tile, k32 chunks, single smem buffer + register prefetch.
// smem: A hi/lo + B hi/lo, each 128 rows x 80B (32 k-elems + 16B pad).
#define PITCH 80
#define AH_OFF 0
#define AL_OFF 10240
#define BH_OFF 20480
#define BL_OFF 30720
#define SMT    40960

__global__ __launch_bounds__(256)
void gemm1_mma(const float* __restrict__ x, const float* __restrict__ b1) {
    if ((int)blockIdx.y >= g_ntiles) return;
    int td = g_tiles[blockIdx.y];
    int e  = td >> 16;
    int m0 = (td & 0xffff) << 7;
    int cnt  = g_count[e];
    int base = g_offset[e];
    const int* toks = g_tok + e * T_TOK;
    int n0 = blockIdx.x * 128;

    __shared__ __align__(128) char sm[SMT];

    int tx = threadIdx.x;
    int lane = tx & 31, wid = tx >> 5;
    int wm = (wid >> 2) * 64, wn = (wid & 3) * 32;    // warp tile 64m x 32n

    // ---- loader coordinates ----
    // A: 128 rows x (32 floats per chunk); 8 threads/row, 4 row-groups
    int aq = tx & 7;                                   // 16B (4-float) slot
    const float* xp[4];
    int arow[4];
    #pragma unroll
    for (int it = 0; it < 4; it++) {
        arow[it] = (tx >> 3) + it * 32;
        int slot = m0 + arow[it];
        int tok = toks[slot < T_TOK ? slot : 0];       // stale slots: any valid token
        xp[it] = x + (size_t)tok * DIM + aq * 4;
    }
    // B: 128 n-rows x (32 bf16 per chunk hi/lo); 4 threads/row, 2 row-groups
    int bq = tx & 3;
    int brow0 = (tx >> 2);                             // + it*64
    const __nv_bfloat16* wh = g_w1_hi + ((size_t)e * HID + n0) * DIM + bq * 8;
    const __nv_bfloat16* wl = g_w1_lo + ((size_t)e * HID + n0) * DIM + bq * 8;

    float acc[4][4][4];
    #pragma unroll
    for (int mi = 0; mi < 4; mi++)
        #pragma unroll
        for (int ni = 0; ni < 4; ni++)
            #pragma unroll
            for (int q = 0; q < 4; q++) acc[mi][ni][q] = 0.0f;

    int g = lane >> 2, tg = lane & 3;                  // fragment coords

    for (int c = 0; c < DIM / 32; c++) {
        int k0 = c * 32;
        // ---- prefetch to registers ----
        float4 ra[4];
        uint4 rbh[2], rbl[2];
        #pragma unroll
        for (int it = 0; it < 4; it++) ra[it] = *(const float4*)(xp[it] + k0);
        #pragma unroll
        for (int it = 0; it < 2; it++) {
            size_t go = (size_t)(brow0 + it * 64) * DIM + k0;
            rbh[it] = *(const uint4*)(wh + go);
            rbl[it] = *(const uint4*)(wl + go);
        }
        __syncthreads();                               // previous chunk consumed
        // ---- store to smem ----
        #pragma unroll
        for (int it = 0; it < 4; it++) {
            uint2 hp, lp;
            __nv_bfloat16 h0 = __float2bfloat16(ra[it].x);
            __nv_bfloat16 h1 = __float2bfloat16(ra[it].y);
            __nv_bfloat16 h2 = __float2bfloat16(ra[it].z);
            __nv_bfloat16 h3 = __float2bfloat16(ra[it].w);
            __nv_bfloat162 p01 = __halves2bfloat162(h0, h1);
            __nv_bfloat162 p23 = __halves2bfloat162(h2, h3);
            hp.x = *(uint32_t*)&p01; hp.y = *(uint32_t*)&p23;
            lp.x = packbf2(ra[it].x - __bfloat162float(h0), ra[it].y - __bfloat162float(h1));
            lp.y = packbf2(ra[it].z - __bfloat162float(h2), ra[it].w - __bfloat162float(h3));
            uint32_t so = (uint32_t)(arow[it] * PITCH + aq * 8);
            *(uint2*)(sm + AH_OFF + so) = hp;
            *(uint2*)(sm + AL_OFF + so) = lp;
        }
        #pragma unroll
        for (int it = 0; it < 2; it++) {
            uint32_t so = (uint32_t)((brow0 + it * 64) * PITCH + bq * 16);
            *(uint4*)(sm + BH_OFF + so) = rbh[it];
            *(uint4*)(sm + BL_OFF + so) = rbl[it];
        }
        __syncthreads();                               // smem ready

        // ---- compute: fragments via direct LDS (PTX-doc coordinates) ----
        #pragma unroll
        for (int k16 = 0; k16 < 2; k16++) {
            uint32_t kb = (uint32_t)(k16 * 32 + tg * 4);
            uint32_t bH[4][2], bL[4][2];
            #pragma unroll
            for (int nj = 0; nj < 4; nj++) {
                uint32_t na = (uint32_t)((wn + nj * 8 + g) * PITCH) + kb;
                bH[nj][0] = *(const uint32_t*)(sm + BH_OFF + na);
                bH[nj][1] = *(const uint32_t*)(sm + BH_OFF + na + 16);
                bL[nj][0] = *(const uint32_t*)(sm + BL_OFF + na);
                bL[nj][1] = *(const uint32_t*)(sm + BL_OFF + na + 16);
            }
            #pragma unroll
            for (int mi = 0; mi < 4; mi++) {
                uint32_t ma = (uint32_t)((wm + mi * 16 + g) * PITCH) + kb;
                uint32_t aH[4], aL[4];
                aH[0] = *(const uint32_t*)(sm + AH_OFF + ma);
                aH[1] = *(const uint32_t*)(sm + AH_OFF + ma + 8 * PITCH);
                aH[2] = *(const uint32_t*)(sm + AH_OFF + ma + 16);
                aH[3] = *(const uint32_t*)(sm + AH_OFF + ma + 8 * PITCH + 16);
                aL[0] = *(const uint32_t*)(sm + AL_OFF + ma);
                aL[1] = *(const uint32_t*)(sm + AL_OFF + ma + 8 * PITCH);
                aL[2] = *(const uint32_t*)(sm + AL_OFF + ma + 16);
                aL[3] = *(const uint32_t*)(sm + AL_OFF + ma + 8 * PITCH + 16);
                #pragma unroll
                for (int nj = 0; nj < 4; nj++) {
                    mma_bf16(acc[mi][nj], aH, bH[nj]);
                    mma_bf16(acc[mi][nj], aH, bL[nj]);
                    mma_bf16(acc[mi][nj], aL, bH[nj]);
                }
            }
        }
    }

    // ---- epilogue: bias + gelu -> fp32 H (guarded, unpadded rows) ----
    #pragma unroll
    for (int mi = 0; mi < 4; mi++) {
        #pragma unroll
        for (int nj = 0; nj < 4; nj++) {
            int col = n0 + wn + nj * 8 + tg * 2;
            #pragma unroll
            for (int half = 0; half < 2; half++) {
                int slot = m0 + wm + mi * 16 + g + half * 8;
                if (slot >= cnt) continue;
                float h0 = gelu_tanh(acc[mi][nj][half * 2 + 0] + b1[e * HID + col]);
                float h1 = gelu_tanh(acc[mi][nj][half * 2 + 1] + b1[e * HID + col + 1]);
                float2 o; o.x = h0; o.y = h1;
                *(float2*)(g_hf + (size_t)(base + slot) * HID + col) = o;
            }
        }
    }
}

// ======================= GEMM2 (R3-proven fp32 SIMT): out += H @ W2 + b2 =======================
#define BM 128
#define BN 128
#define BK 32

__global__ __launch_bounds__(256, 2)
void gemm2_kernel(const float* __restrict__ W2,
                  const float* __restrict__ b2,
                  float* __restrict__ out) {
    int e   = blockIdx.z;
    int cnt = g_count[e];
    int r0  = blockIdx.y * BM;
    if (r0 >= cnt) return;
    int n0   = blockIdx.x * BN;
    int base = g_offset[e];
    const int* toks = g_tok + e * T_TOK;
    const float* Wb = W2 + (size_t)e * HID * DIM;

    __shared__ float As[BK][BM];
    __shared__ float Bs[BK][BN];

    int tx = threadIdx.x;
    int tr = tx >> 4, tc = tx & 15;

    float acc[8][8];
    #pragma unroll
    for (int i = 0; i < 8; i++)
        #pragma unroll
        for (int j = 0; j < 8; j++) acc[i][j] = 0.0f;

    for (int k0 = 0; k0 < HID; k0 += BK) {
        #pragma unroll
        for (int i = 0; i < 4; i++) {
            int idx = tx + 256 * i;
            int m = idx >> 3, kq = idx & 7;
            int row = base + r0 + m;
            if (row >= 2 * T_TOK) row = 2 * T_TOK - 1;   // clamp (stale-safe)
            float4 v = *(const float4*)(g_hf + (size_t)row * HID + k0 + kq * 4);
            As[kq * 4 + 0][m] = v.x; As[kq * 4 + 1][m] = v.y;
            As[kq * 4 + 2][m] = v.z; As[kq * 4 + 3][m] = v.w;
        }
        #pragma unroll
        for (int i = 0; i < 4; i++) {
            int idx = tx + 256 * i;
            int kk = idx >> 5, n4 = idx & 31;
            *(float4*)&Bs[kk][n4 * 4] =
                *(const float4*)(Wb + (size_t)(k0 + kk) * DIM + n0 + n4 * 4);
        }
        __syncthreads();
        #pragma unroll
        for (int k = 0; k < BK; k++) {
            float a[8], b[8];
            *(float4*)&a[0] = *(const float4*)&As[k][tr * 4];
            *(float4*)&a[4] = *(const float4*)&As[k][64 + tr * 4];
            *(float4*)&b[0] = *(const float4*)&Bs[k][tc * 4];
            *(float4*)&b[4] = *(const float4*)&Bs[k][64 + tc * 4];
            #pragma unroll
            for (int i = 0; i < 8; i++)
                #pragma unroll
                for (int j = 0; j < 8; j++)
                    acc[i][j] += a[i] * b[j];
        }
        __syncthreads();
    }

    const float* b2e = b2 + (size_t)e * DIM;
    #pragma unroll
    for (int i = 0; i < 8; i++) {
        int m = (i < 4) ? (tr * 4 + i) : (64 + tr * 4 + (i - 4));
        int slot = r0 + m;
        if (slot >= cnt) continue;
        int tok = toks[slot];
        float* op = out + (size_t)tok * DIM + n0;
        #pragma unroll
        for (int j = 0; j < 8; j++) {
            int n = (j < 4) ? (tc * 4 + j) : (64 + tc * 4 + (j - 4));
            atomicAdd(&op[n], acc[i][j] + b2e[n0 + n]);
        }
    }
}

// ======================= launch =======================
extern "C" void kernel_launch(void* const* d_in, const int* in_sizes, int n_in,
                              void* d_out, int out_size) {
    const float* x  = (const float*)d_in[0];
    const float* Wg = (const float*)d_in[1];
    const float* bg = (const float*)d_in[2];
    const float* W1 = (const float*)d_in[3];
    const float* b1 = (const float*)d_in[4];
    const float* W2 = (const float*)d_in[5];
    const float* b2 = (const float*)d_in[6];
    float* out = (float*)d_out;

    int total = T_TOK * DIM;
    init_kernel<<<(total + 255) / 256, 256>>>(out);
    gate_kernel<<<T_TOK, 128>>>(x, Wg, bg, out, out_size);
    prefix_kernel<<<1, 1>>>();
    transpose_split_w1<<<dim3(HID / 32, DIM / 32, NE), dim3(32, 8)>>>(W1);

    gemm1_mma<<<dim3(HID / 128, 80), 256>>>(x, b1);
    gemm2_kernel<<<dim3(DIM / BN, T_TOK / BM, NE), 256>>>(W2, b2, out);
}

// round 17
// speedup vs baseline: 1.8945x; 1.4228x over previous
#include <cuda_runtime.h>
#include <cuda_bf16.h>
#include <stdint.h>
#include <math.h>

#define T_TOK 4096
#define DIM   512
#define HID   2048
#define NE    16

// ======================= device scratch (static, force-aligned) =======================
// RULE (root cause of R5-R16 failures): these symbols are ONLY referenced inside
// device code — NEVER passed as kernel arguments from host (host-side shadow address).
__device__ __align__(128) int   g_count[NE];
__device__ __align__(128) int   g_offset[NE];
__device__ __align__(128) int   g_ntiles;
__device__ __align__(128) int   g_tiles[128];
__device__ __align__(128) int   g_tok[NE * T_TOK];
__device__ __align__(128) float g_hf[(size_t)(2 * T_TOK + 128) * HID];
__device__ __align__(128) __nv_bfloat16 g_w_hi[(size_t)NE * HID * DIM];  // shared: W1^T then W2^T
__device__ __align__(128) __nv_bfloat16 g_w_lo[(size_t)NE * HID * DIM];

// ======================= helpers =======================
__device__ __forceinline__ void mma_bf16(float* d, const uint32_t* a, const uint32_t* b) {
    asm volatile(
        "mma.sync.aligned.m16n8k16.row.col.f32.bf16.bf16.f32 "
        "{%0,%1,%2,%3}, {%4,%5,%6,%7}, {%8,%9}, {%0,%1,%2,%3};"
        : "+f"(d[0]), "+f"(d[1]), "+f"(d[2]), "+f"(d[3])
        : "r"(a[0]), "r"(a[1]), "r"(a[2]), "r"(a[3]), "r"(b[0]), "r"(b[1]));
}
__device__ __forceinline__ float gelu_tanh(float v) {
    float u = 0.7978845608028654f * (v + 0.044715f * v * v * v);
    return 0.5f * v * (1.0f + tanhf(u));
}
__device__ __forceinline__ uint32_t packbf2(float a, float b) {
    __nv_bfloat162 t = __floats2bfloat162_rn(a, b);
    return *(uint32_t*)&t;
}

// ======================= init: zero out region + counters =======================
__global__ void init_kernel(float* out) {
    int idx = blockIdx.x * blockDim.x + threadIdx.x;
    if (idx < T_TOK * DIM) out[idx] = 0.0f;
    if (idx < NE) g_count[idx] = 0;
}

// ======================= gate (proven) =======================
__global__ void gate_kernel(const float* __restrict__ x,
                            const float* __restrict__ Wg,
                            const float* __restrict__ bg,
                            float* __restrict__ out, int out_size) {
    int t = blockIdx.x;
    int tid = threadIdx.x;          // 128 threads
    int e = tid & 15;
    int g = tid >> 4;               // 0..7
    const float* xr = x + (size_t)t * DIM;

    float s = 0.0f;
    for (int d = g; d < DIM; d += 8)
        s += xr[d] * Wg[d * NE + e];

    __shared__ float buf[128];
    __shared__ float logits[NE];
    buf[tid] = s;
    __syncthreads();
    if (g == 0) {
        float l = bg[e];
        #pragma unroll
        for (int j = 0; j < 8; j++) l += buf[j * 16 + e];
        logits[e] = l;
    }
    __syncthreads();

    if (tid == 0) {
        int i0 = 0; float v0 = logits[0];
        #pragma unroll
        for (int k = 1; k < NE; k++)
            if (logits[k] > v0) { v0 = logits[k]; i0 = k; }
        int i1 = -1; float v1 = -1e30f;
        #pragma unroll
        for (int k = 0; k < NE; k++)
            if (k != i0 && logits[k] > v1) { v1 = logits[k]; i1 = k; }

        float e1 = __expf(v1 - v0);
        float inv = 1.0f / (1.0f + e1);

        const int base_idx = T_TOK * DIM;
        const int base_sc  = T_TOK * DIM + T_TOK * 2;
        if (out_size >= base_idx + T_TOK * 2) {
            out[base_idx + t * 2 + 0] = (float)i0;
            out[base_idx + t * 2 + 1] = (float)i1;
        }
        if (out_size >= base_sc + T_TOK * 2) {
            out[base_sc + t * 2 + 0] = inv;
            out[base_sc + t * 2 + 1] = e1 * inv;
        }

        int slot0 = atomicAdd(&g_count[i0], 1);
        g_tok[i0 * T_TOK + slot0] = t;
        int slot1 = atomicAdd(&g_count[i1], 1);
        g_tok[i1 * T_TOK + slot1] = t;
    }
}

// ======================= prefix: unpadded offsets + tile list =======================
__global__ void prefix_kernel() {
    if (threadIdx.x == 0 && blockIdx.x == 0) {
        int s = 0, nt = 0;
        for (int e = 0; e < NE; e++) {
            g_offset[e] = s;
            int cnt = g_count[e];
            for (int m = 0; m < cnt; m += 128) g_tiles[nt++] = (e << 16) | (m >> 7);
            s += cnt;
        }
        g_ntiles = nt;
    }
}

// ======================= weight transpose + fp32->bf16 hi/lo split =======================
// src [e][R][C] row-major -> g_w_hi/g_w_lo [e][C][R]  (dst hardcoded: device-symbol rule)
__global__ void transpose_w(const float* __restrict__ src, int R, int C) {
    __shared__ float tile[32][33];
    int e = blockIdx.z;
    const float* S = src + (size_t)e * R * C;
    int c0 = blockIdx.x * 32, r0 = blockIdx.y * 32;
    int tx = threadIdx.x, ty = threadIdx.y;
    #pragma unroll
    for (int i = 0; i < 4; i++)
        tile[ty + i * 8][tx] = S[(size_t)(r0 + ty + i * 8) * C + c0 + tx];
    __syncthreads();
    size_t Dbase = (size_t)e * R * C;
    #pragma unroll
    for (int i = 0; i < 4; i++) {
        int c = c0 + ty + i * 8;
        float v = tile[tx][ty + i * 8];
        size_t o = Dbase + (size_t)c * R + r0 + tx;
        __nv_bfloat16 h = __float2bfloat16(v);
        g_w_hi[o] = h;
        g_w_lo[o] = __float2bfloat16(v - __bfloat162float(h));
    }
}

// ======================= shared GEMM geometry =======================
#define PITCH 80
#define AH_OFF 0
#define AL_OFF 10240
#define BH_OFF 20480
#define BL_OFF 30720
#define SMT    40960

// ======================= unified grouped GEMM (one symbol, launched twice) ==========
// mode 1: A = x rows gathered via toks [kTot=DIM], epilogue bias+gelu -> g_hf   [nTot=HID]
// mode 2: A = g_hf compact rows        [kTot=HID], epilogue atomicAdd -> out    [nTot=DIM]
// All g_* symbols resolved INSIDE device code; kernel args are harness pointers + scalars only.
__global__ __launch_bounds__(256)
void gemm_mma(int kTot, int nTot, int mode,
              const float* __restrict__ x,
              const float* __restrict__ bias,
              float* __restrict__ out) {
    if ((int)blockIdx.y >= g_ntiles) return;
    int td = g_tiles[blockIdx.y];
    int e  = td >> 16;
    int m0 = (td & 0xffff) << 7;
    int cnt  = g_count[e];
    int base = g_offset[e];
    const int* toks = g_tok + e * T_TOK;
    int n0 = blockIdx.x * 128;

    __shared__ __align__(128) char sm[SMT];

    int tx = threadIdx.x;
    int lane = tx & 31, wid = tx >> 5;
    int wm = (wid >> 2) * 64, wn = (wid & 3) * 32;

    // ---- A row pointers (device-side symbol selection) ----
    const float* Asrc = (mode == 1) ? x : g_hf;
    int aq = tx & 7;
    const float* xp[4];
    int arow[4];
    #pragma unroll
    for (int it = 0; it < 4; it++) {
        arow[it] = (tx >> 3) + it * 32;
        int slot = m0 + arow[it];
        const float* ap;
        if (mode == 1) {
            int tok = toks[slot < T_TOK ? slot : 0];
            ap = Asrc + (size_t)tok * kTot;
        } else {
            if (slot >= cnt) slot = cnt - 1;
            ap = Asrc + (size_t)(base + slot) * kTot;
        }
        xp[it] = ap + aq * 4;
    }
    int bq = tx & 3;
    int brow0 = (tx >> 2);
    const __nv_bfloat16* wh = g_w_hi + ((size_t)e * nTot + n0) * kTot + bq * 8;
    const __nv_bfloat16* wl = g_w_lo + ((size_t)e * nTot + n0) * kTot + bq * 8;

    float acc[4][4][4];
    #pragma unroll
    for (int mi = 0; mi < 4; mi++)
        #pragma unroll
        for (int ni = 0; ni < 4; ni++)
            #pragma unroll
            for (int q = 0; q < 4; q++) acc[mi][ni][q] = 0.0f;

    int g = lane >> 2, tg = lane & 3;

    int nChunks = kTot >> 5;
    for (int c = 0; c < nChunks; c++) {
        int k0 = c * 32;
        float4 ra[4];
        uint4 rbh[2], rbl[2];
        #pragma unroll
        for (int it = 0; it < 4; it++) ra[it] = *(const float4*)(xp[it] + k0);
        #pragma unroll
        for (int it = 0; it < 2; it++) {
            size_t go = (size_t)(brow0 + it * 64) * kTot + k0;
            rbh[it] = *(const uint4*)(wh + go);
            rbl[it] = *(const uint4*)(wl + go);
        }
        __syncthreads();
        #pragma unroll
        for (int it = 0; it < 4; it++) {
            uint2 hp, lp;
            __nv_bfloat16 h0 = __float2bfloat16(ra[it].x);
            __nv_bfloat16 h1 = __float2bfloat16(ra[it].y);
            __nv_bfloat16 h2 = __float2bfloat16(ra[it].z);
            __nv_bfloat16 h3 = __float2bfloat16(ra[it].w);
            __nv_bfloat162 p01 = __halves2bfloat162(h0, h1);
            __nv_bfloat162 p23 = __halves2bfloat162(h2, h3);
            hp.x = *(uint32_t*)&p01; hp.y = *(uint32_t*)&p23;
            lp.x = packbf2(ra[it].x - __bfloat162float(h0), ra[it].y - __bfloat162float(h1));
            lp.y = packbf2(ra[it].z - __bfloat162float(h2), ra[it].w - __bfloat162float(h3));
            uint32_t so = (uint32_t)(arow[it] * PITCH + aq * 8);
            *(uint2*)(sm + AH_OFF + so) = hp;
            *(uint2*)(sm + AL_OFF + so) = lp;
        }
        #pragma unroll
        for (int it = 0; it < 2; it++) {
            uint32_t so = (uint32_t)((brow0 + it * 64) * PITCH + bq * 16);
            *(uint4*)(sm + BH_OFF + so) = rbh[it];
            *(uint4*)(sm + BL_OFF + so) = rbl[it];
        }
        __syncthreads();

        #pragma unroll
        for (int k16 = 0; k16 < 2; k16++) {
            uint32_t kb = (uint32_t)(k16 * 32 + tg * 4);
            uint32_t bH[4][2], bL[4][2];
            #pragma unroll
            for (int nj = 0; nj < 4; nj++) {
                uint32_t na = (uint32_t)((wn + nj * 8 + g) * PITCH) + kb;
                bH[nj][0] = *(const uint32_t*)(sm + BH_OFF + na);
                bH[nj][1] = *(const uint32_t*)(sm + BH_OFF + na + 16);
                bL[nj][0] = *(const uint32_t*)(sm + BL_OFF + na);
                bL[nj][1] = *(const uint32_t*)(sm + BL_OFF + na + 16);
            }
            #pragma unroll
            for (int mi = 0; mi < 4; mi++) {
                uint32_t ma = (uint32_t)((wm + mi * 16 + g) * PITCH) + kb;
                uint32_t aH[4], aL[4];
                aH[0] = *(const uint32_t*)(sm + AH_OFF + ma);
                aH[1] = *(const uint32_t*)(sm + AH_OFF + ma + 8 * PITCH);
                aH[2] = *(const uint32_t*)(sm + AH_OFF + ma + 16);
                aH[3] = *(const uint32_t*)(sm + AH_OFF + ma + 8 * PITCH + 16);
                aL[0] = *(const uint32_t*)(sm + AL_OFF + ma);
                aL[1] = *(const uint32_t*)(sm + AL_OFF + ma + 8 * PITCH);
                aL[2] = *(const uint32_t*)(sm + AL_OFF + ma + 16);
                aL[3] = *(const uint32_t*)(sm + AL_OFF + ma + 8 * PITCH + 16);
                #pragma unroll
                for (int nj = 0; nj < 4; nj++) {
                    mma_bf16(acc[mi][nj], aH, bH[nj]);
                    mma_bf16(acc[mi][nj], aH, bL[nj]);
                    mma_bf16(acc[mi][nj], aL, bH[nj]);
                }
            }
        }
    }

    // ---- epilogue (mode-resolved) ----
    #pragma unroll
    for (int mi = 0; mi < 4; mi++) {
        #pragma unroll
        for (int nj = 0; nj < 4; nj++) {
            int col = n0 + wn + nj * 8 + tg * 2;
            #pragma unroll
            for (int half = 0; half < 2; half++) {
                int slot = m0 + wm + mi * 16 + g + half * 8;
                if (slot >= cnt) continue;
                float v0 = acc[mi][nj][half * 2 + 0] + bias[e * nTot + col];
                float v1 = acc[mi][nj][half * 2 + 1] + bias[e * nTot + col + 1];
                if (mode == 1) {
                    float2 o;
                    o.x = gelu_tanh(v0);
                    o.y = gelu_tanh(v1);
                    *(float2*)(g_hf + (size_t)(base + slot) * HID + col) = o;
                } else {
                    int tok = toks[slot];
                    float* op = out + (size_t)tok * DIM + col;
                    atomicAdd(op,     v0);
                    atomicAdd(op + 1, v1);
                }
            }
        }
    }
}

// ======================= launch =======================
// AUDIT: every kernel arg below is a harness pointer (d_in/d_out) or a scalar.
// No __device__ symbol ever appears as a host-side kernel argument.
extern "C" void kernel_launch(void* const* d_in, const int* in_sizes, int n_in,
                              void* d_out, int out_size) {
    const float* x  = (const float*)d_in[0];
    const float* Wg = (const float*)d_in[1];
    const float* bg = (const float*)d_in[2];
    const float* W1 = (const float*)d_in[3];
    const float* b1 = (const float*)d_in[4];
    const float* W2 = (const float*)d_in[5];
    const float* b2 = (const float*)d_in[6];
    float* out = (float*)d_out;

    int total = T_TOK * DIM;
    init_kernel<<<(total + 255) / 256, 256>>>(out);
    gate_kernel<<<T_TOK, 128>>>(x, Wg, bg, out, out_size);
    prefix_kernel<<<1, 1>>>();

    // W1 [E][D][H] -> g_w [E][H][D]; gemm pass 1 (H = gelu(x@W1+b1))
    transpose_w<<<dim3(HID / 32, DIM / 32, NE), dim3(32, 8)>>>(W1, DIM, HID);
    gemm_mma<<<dim3(HID / 128, 80), 256>>>(DIM, HID, 1, x, b1, out);

    // W2 [E][H][D] -> g_w [E][D][H]; gemm pass 2 (out += H@W2+b2, scattered)
    transpose_w<<<dim3(DIM / 32, HID / 32, NE), dim3(32, 8)>>>(W2, HID, DIM);
    gemm_mma<<<dim3(DIM / 128, 80), 256>>>(HID, DIM, 2, x, b2, out);
}